// round 9
// baseline (speedup 1.0000x reference)
#include <cuda_runtime.h>

#define WSZ 64
#define HD 64
#define SHIFT 32
#define WTOT 8192
#define NWIN 128

typedef unsigned long long u64;
__device__ __forceinline__ u64 pk2(float a, float b) {
    u64 r; asm("mov.b64 %0, {%1, %2};" : "=l"(r) : "f"(a), "f"(b)); return r;
}
__device__ __forceinline__ void upk2(u64 x, float &a, float &b) {
    asm("mov.b64 {%0, %1}, %2;" : "=f"(a), "=f"(b) : "l"(x));
}
__device__ __forceinline__ void ffma2(u64 &d, u64 a, u64 b) {
    asm("fma.rn.f32x2 %0, %1, %2, %0;" : "+l"(d) : "l"(a), "l"(b));
}
// swizzled index into [64][64] transposed tiles; keeps 16B alignment
__device__ __forceinline__ int SW(int row, int f) {
    return (row << 6) + (f ^ ((row & 7) << 2));
}

__global__ __launch_bounds__(64)
void swin_attn8(const float* __restrict__ q, const float* __restrict__ k,
                const float* __restrict__ v, const float* __restrict__ rel,
                float* __restrict__ xout, float* __restrict__ aout)
{
    __shared__ float Qt[WSZ * WSZ];   // [kdim][row] swizzled; later Pt[m][row]
    __shared__ float Kt[WSZ * WSZ];   // [kdim][col] swizzled
    __shared__ float Vs[WSZ * WSZ];   // [m][col] linear

    const int t = threadIdx.x, blk = blockIdx.x;
    const int w = blk & (NWIN - 1);
    const size_t base = (size_t)(blk >> 7) * (size_t)(WTOT * HD);
    const int wstart = w * WSZ;
    const int rb = t >> 3, c4 = (t & 7) << 2, rot = (t >> 1) & 3;

    // ---- load: Q/K transposed+swizzled (roll folded into row index), V linear
    #pragma unroll
    for (int i = 0; i < 8; i++) {
        int r = rb + 8 * i;
        int g = (wstart + r + SHIFT) & (WTOT - 1);
        size_t off = base + (size_t)g * HD + c4;
        #pragma unroll
        for (int h = 0; h < 2; h++) {
            float4 qv = *(const float4*)(q + off + 32 * h);
            float4 kv = *(const float4*)(k + off + 32 * h);
            float4 vv = *(const float4*)(v + off + 32 * h);
            float qa[4] = {qv.x * 0.125f, qv.y * 0.125f, qv.z * 0.125f, qv.w * 0.125f};
            float ka[4] = {kv.x, kv.y, kv.z, kv.w};
            #pragma unroll
            for (int jj = 0; jj < 4; jj++) {
                int jr = (jj + rot) & 3;              // rotation -> conflict-free
                Qt[SW(c4 + 32 * h + jr, r)] = qa[jr];
                Kt[SW(c4 + 32 * h + jr, r)] = ka[jr];
            }
            *(float4*)(Vs + r * HD + c4 + 32 * h) = vv;
        }
    }
    __syncthreads();

    const int r0 = rb << 3, c0 = c4;

    // ---- GEMM1: S = (Q*scale) @ K^T, 8 rows x 8 cols per thread
    u64 acc[8][4];
    #pragma unroll
    for (int j = 0; j < 8; j++) { acc[j][0]=acc[j][1]=acc[j][2]=acc[j][3]=0ull; }
    #pragma unroll 4
    for (int kk = 0; kk < WSZ; kk++) {
        float4 k0 = *(const float4*)(Kt + SW(kk, c0));
        float4 k1 = *(const float4*)(Kt + SW(kk, c0 + 32));
        ulonglong2 qA = *(const ulonglong2*)(Qt + SW(kk, r0));
        ulonglong2 qB = *(const ulonglong2*)(Qt + SW(kk, r0 + 4));
        u64 qp[4] = {qA.x, qA.y, qB.x, qB.y};
        u64 kd[8] = {pk2(k0.x,k0.x), pk2(k0.y,k0.y), pk2(k0.z,k0.z), pk2(k0.w,k0.w),
                     pk2(k1.x,k1.x), pk2(k1.y,k1.y), pk2(k1.z,k1.z), pk2(k1.w,k1.w)};
        #pragma unroll
        for (int j = 0; j < 8; j++)
            #pragma unroll
            for (int p = 0; p < 4; p++) ffma2(acc[j][p], qp[p], kd[j]);
    }
    float sv[8][8];
    #pragma unroll
    for (int j = 0; j < 8; j++)
        #pragma unroll
        for (int p = 0; p < 4; p++) upk2(acc[j][p], sv[2*p][j], sv[2*p+1][j]);

    // ---- bias + shift mask
    const int dbA = r0 - c0 + 60, dbB = dbA - 32;
    float bA[11], bB[11];
    #pragma unroll
    for (int d = 0; d < 11; d++) { bA[d] = __ldg(rel + dbA + d); bB[d] = __ldg(rel + dbB + d); }
    const bool lastw = (w == NWIN - 1);
    const float m0 = (lastw && rb >= 4) ? -100.0f : 0.0f;
    const float m1 = (lastw && rb <  4) ? -100.0f : 0.0f;
    #pragma unroll
    for (int i = 0; i < 8; i++)
        #pragma unroll
        for (int d = 0; d < 4; d++) {
            sv[i][d]     += bA[i - d + 3] + m0;
            sv[i][d + 4] += bB[i - d + 3] + m1;
        }

    // ---- softmax per row (8 cols in-thread, xor-shuffle over 8-lane row group)
    #pragma unroll
    for (int i = 0; i < 8; i++) {
        float mx = sv[i][0];
        #pragma unroll
        for (int j = 1; j < 8; j++) mx = fmaxf(mx, sv[i][j]);
        mx = fmaxf(mx, __shfl_xor_sync(~0u, mx, 1));
        mx = fmaxf(mx, __shfl_xor_sync(~0u, mx, 2));
        mx = fmaxf(mx, __shfl_xor_sync(~0u, mx, 4));
        float sum = 0.f;
        #pragma unroll
        for (int j = 0; j < 8; j++) { sv[i][j] = __expf(sv[i][j] - mx); sum += sv[i][j]; }
        sum += __shfl_xor_sync(~0u, sum, 1);
        sum += __shfl_xor_sync(~0u, sum, 2);
        sum += __shfl_xor_sync(~0u, sum, 4);
        float inv = __fdividef(1.f, sum);
        #pragma unroll
        for (int j = 0; j < 8; j++) sv[i][j] *= inv;
    }

    // ---- attn store + P^T into Qt (swizzled, rotated)
    const size_t aoff = (size_t)blk * (WSZ * WSZ);
    #pragma unroll
    for (int i = 0; i < 8; i++) {
        *(float4*)(aout + aoff + (size_t)(r0+i)*WSZ + c0)      = make_float4(sv[i][0],sv[i][1],sv[i][2],sv[i][3]);
        *(float4*)(aout + aoff + (size_t)(r0+i)*WSZ + c0 + 32) = make_float4(sv[i][4],sv[i][5],sv[i][6],sv[i][7]);
    }
    __syncthreads();                      // all GEMM1 reads of Qt done
    #pragma unroll
    for (int h = 0; h < 2; h++)
        #pragma unroll
        for (int d = 0; d < 4; d++) {
            int dr = (d + rot) & 3;
            int j = dr + 4 * h, c = c0 + 32 * h + dr;
            *(float4*)(Qt + SW(c, r0))     = make_float4(sv[0][j], sv[1][j], sv[2][j], sv[3][j]);
            *(float4*)(Qt + SW(c, r0 + 4)) = make_float4(sv[4][j], sv[5][j], sv[6][j], sv[7][j]);
        }
    __syncthreads();

    // ---- GEMM2: O = P @ V
    u64 oa[8][4];
    #pragma unroll
    for (int j = 0; j < 8; j++) { oa[j][0]=oa[j][1]=oa[j][2]=oa[j][3]=0ull; }
    #pragma unroll 4
    for (int m = 0; m < WSZ; m++) {
        float4 v0 = *(const float4*)(Vs + m * HD + c0);
        float4 v1 = *(const float4*)(Vs + m * HD + c0 + 32);
        ulonglong2 pA = *(const ulonglong2*)(Qt + SW(m, r0));
        ulonglong2 pB = *(const ulonglong2*)(Qt + SW(m, r0 + 4));
        u64 pp[4] = {pA.x, pA.y, pB.x, pB.y};
        u64 vd[8] = {pk2(v0.x,v0.x), pk2(v0.y,v0.y), pk2(v0.z,v0.z), pk2(v0.w,v0.w),
                     pk2(v1.x,v1.x), pk2(v1.y,v1.y), pk2(v1.z,v1.z), pk2(v1.w,v1.w)};
        #pragma unroll
        for (int j = 0; j < 8; j++)
            #pragma unroll
            for (int p = 0; p < 4; p++) ffma2(oa[j][p], pp[p], vd[j]);
    }

    // ---- output store (roll folded back in)
    #pragma unroll
    for (int p = 0; p < 4; p++) {
        float o[2][8];
        #pragma unroll
        for (int j = 0; j < 8; j++) upk2(oa[j][p], o[0][j], o[1][j]);
        #pragma unroll
        for (int s = 0; s < 2; s++) {
            int g = (wstart + r0 + 2*p + s + SHIFT) & (WTOT - 1);
            *(float4*)(xout + base + (size_t)g*HD + c0)      = make_float4(o[s][0],o[s][1],o[s][2],o[s][3]);
            *(float4*)(xout + base + (size_t)g*HD + c0 + 32) = make_float4(o[s][4],o[s][5],o[s][6],o[s][7]);
        }
    }
}

extern "C" void kernel_launch(void* const* d_in, const int* in_sizes, int n_in,
                              void* d_out, int out_size) {
    const float* q   = (const float*)d_in[0];
    const float* k   = (const float*)d_in[1];
    const float* v   = (const float*)d_in[2];
    const float* rel = (const float*)d_in[3];
    const int B = in_sizes[0] / (WTOT * HD);
    float* xout = (float*)d_out;
    float* aout = xout + (size_t)B * WTOT * HD;

    // Raise the L1/shared carveout so 4 CTAs (4x48KB=192KB <= 228KB) fit per SM.
    // Default carveout (~100KB) capped residency at 2 CTAs -> occ 12%, issue 48%.
    cudaFuncSetAttribute(swin_attn8,
                         cudaFuncAttributePreferredSharedMemoryCarveout, 100);

    swin_attn8<<<B * NWIN, 64>>>(q, k, v, rel, xout, aout);
}

// round 12
// speedup vs baseline: 1.0862x; 1.0862x over previous
#include <cuda_runtime.h>

#define WSZ 64
#define HD 64
#define SHIFT 32
#define WTOT 8192
#define NWIN 128

typedef unsigned long long u64;
__device__ __forceinline__ u64 pk2(float a, float b) {
    u64 r; asm("mov.b64 %0, {%1, %2};" : "=l"(r) : "f"(a), "f"(b)); return r;
}
__device__ __forceinline__ void upk2(u64 x, float &a, float &b) {
    asm("mov.b64 {%0, %1}, %2;" : "=f"(a), "=f"(b) : "l"(x));
}
__device__ __forceinline__ void ffma2(u64 &d, u64 a, u64 b) {
    asm("fma.rn.f32x2 %0, %1, %2, %0;" : "+l"(d) : "l"(a), "l"(b));
}
// swizzled index into [64][64] transposed tiles; keeps 16B alignment
__device__ __forceinline__ int SW(int row, int f) {
    return (row << 6) + (f ^ ((row & 7) << 2));
}

__global__ __launch_bounds__(64, 7)
void swin_attn8(const float* __restrict__ q, const float* __restrict__ k,
                const float* __restrict__ v, const float* __restrict__ rel,
                float* __restrict__ xout, float* __restrict__ aout)
{
    __shared__ float Qt[WSZ * WSZ];   // [kdim][row] swizzled; later Pt[m][row]
    __shared__ float KV[WSZ * WSZ];   // phase 1: Kt [kdim][col] swizzled
                                      // phase 2: Vs [m][col] linear (K dead after GEMM1)

    const int t = threadIdx.x, blk = blockIdx.x;
    const int w = blk & (NWIN - 1);
    const size_t base = (size_t)(blk >> 7) * (size_t)(WTOT * HD);
    const int wstart = w * WSZ;
    const int rb = t >> 3, c4 = (t & 7) << 2, rot = (t >> 1) & 3;

    // ---- load: Q/K transposed+swizzled (roll folded into row index). V deferred.
    #pragma unroll
    for (int i = 0; i < 8; i++) {
        int r = rb + 8 * i;
        int g = (wstart + r + SHIFT) & (WTOT - 1);
        size_t off = base + (size_t)g * HD + c4;
        #pragma unroll
        for (int h = 0; h < 2; h++) {
            float4 qv = *(const float4*)(q + off + 32 * h);
            float4 kv = *(const float4*)(k + off + 32 * h);
            float qa[4] = {qv.x * 0.125f, qv.y * 0.125f, qv.z * 0.125f, qv.w * 0.125f};
            float ka[4] = {kv.x, kv.y, kv.z, kv.w};
            #pragma unroll
            for (int jj = 0; jj < 4; jj++) {
                int jr = (jj + rot) & 3;              // rotation -> conflict-free STS
                Qt[SW(c4 + 32 * h + jr, r)] = qa[jr];
                KV[SW(c4 + 32 * h + jr, r)] = ka[jr];
            }
        }
    }
    __syncthreads();

    const int r0 = rb << 3, c0 = c4;

    // ---- GEMM1: S = (Q*scale) @ K^T, 8 rows x 8 cols per thread
    u64 acc[8][4];
    #pragma unroll
    for (int j = 0; j < 8; j++) { acc[j][0]=acc[j][1]=acc[j][2]=acc[j][3]=0ull; }
    #pragma unroll 4
    for (int kk = 0; kk < WSZ; kk++) {
        float4 k0 = *(const float4*)(KV + SW(kk, c0));
        float4 k1 = *(const float4*)(KV + SW(kk, c0 + 32));
        ulonglong2 qA = *(const ulonglong2*)(Qt + SW(kk, r0));
        ulonglong2 qB = *(const ulonglong2*)(Qt + SW(kk, r0 + 4));
        u64 qp[4] = {qA.x, qA.y, qB.x, qB.y};
        u64 kd[8] = {pk2(k0.x,k0.x), pk2(k0.y,k0.y), pk2(k0.z,k0.z), pk2(k0.w,k0.w),
                     pk2(k1.x,k1.x), pk2(k1.y,k1.y), pk2(k1.z,k1.z), pk2(k1.w,k1.w)};
        #pragma unroll
        for (int j = 0; j < 8; j++)
            #pragma unroll
            for (int p = 0; p < 4; p++) ffma2(acc[j][p], qp[p], kd[j]);
    }
    float sv[8][8];
    #pragma unroll
    for (int j = 0; j < 8; j++)
        #pragma unroll
        for (int p = 0; p < 4; p++) upk2(acc[j][p], sv[2*p][j], sv[2*p+1][j]);

    // ---- bias + shift mask
    const int dbA = r0 - c0 + 60, dbB = dbA - 32;
    float bA[11], bB[11];
    #pragma unroll
    for (int d = 0; d < 11; d++) { bA[d] = __ldg(rel + dbA + d); bB[d] = __ldg(rel + dbB + d); }
    const bool lastw = (w == NWIN - 1);
    const float m0 = (lastw && rb >= 4) ? -100.0f : 0.0f;
    const float m1 = (lastw && rb <  4) ? -100.0f : 0.0f;
    #pragma unroll
    for (int i = 0; i < 8; i++)
        #pragma unroll
        for (int d = 0; d < 4; d++) {
            sv[i][d]     += bA[i - d + 3] + m0;
            sv[i][d + 4] += bB[i - d + 3] + m1;
        }

    // ---- softmax per row (8 cols in-thread, xor-shuffle over 8-lane row group)
    #pragma unroll
    for (int i = 0; i < 8; i++) {
        float mx = sv[i][0];
        #pragma unroll
        for (int j = 1; j < 8; j++) mx = fmaxf(mx, sv[i][j]);
        mx = fmaxf(mx, __shfl_xor_sync(~0u, mx, 1));
        mx = fmaxf(mx, __shfl_xor_sync(~0u, mx, 2));
        mx = fmaxf(mx, __shfl_xor_sync(~0u, mx, 4));
        float sum = 0.f;
        #pragma unroll
        for (int j = 0; j < 8; j++) { sv[i][j] = __expf(sv[i][j] - mx); sum += sv[i][j]; }
        sum += __shfl_xor_sync(~0u, sum, 1);
        sum += __shfl_xor_sync(~0u, sum, 2);
        sum += __shfl_xor_sync(~0u, sum, 4);
        float inv = __fdividef(1.f, sum);
        #pragma unroll
        for (int j = 0; j < 8; j++) sv[i][j] *= inv;
    }

    // ---- wait until ALL warps finished reading Qt (GEMM1) -> both arrays reusable
    __syncthreads();

    // ---- issue deferred V loads first (long-latency LDGs in flight while we store)
    float4 vr[8][2];
    #pragma unroll
    for (int i = 0; i < 8; i++) {
        int r = rb + 8 * i;
        int g = (wstart + r + SHIFT) & (WTOT - 1);
        size_t off = base + (size_t)g * HD + c4;
        vr[i][0] = *(const float4*)(v + off);
        vr[i][1] = *(const float4*)(v + off + 32);
    }

    // ---- attn global store + P^T into Qt (swizzled, rotated)
    const size_t aoff = (size_t)blk * (WSZ * WSZ);
    #pragma unroll
    for (int i = 0; i < 8; i++) {
        *(float4*)(aout + aoff + (size_t)(r0+i)*WSZ + c0)      = make_float4(sv[i][0],sv[i][1],sv[i][2],sv[i][3]);
        *(float4*)(aout + aoff + (size_t)(r0+i)*WSZ + c0 + 32) = make_float4(sv[i][4],sv[i][5],sv[i][6],sv[i][7]);
    }
    #pragma unroll
    for (int h = 0; h < 2; h++)
        #pragma unroll
        for (int d = 0; d < 4; d++) {
            int dr = (d + rot) & 3;
            int j = dr + 4 * h, c = c0 + 32 * h + dr;
            *(float4*)(Qt + SW(c, r0))     = make_float4(sv[0][j], sv[1][j], sv[2][j], sv[3][j]);
            *(float4*)(Qt + SW(c, r0 + 4)) = make_float4(sv[4][j], sv[5][j], sv[6][j], sv[7][j]);
        }

    // ---- store V into KV (linear Vs layout; quarter-warp phases cover all banks)
    #pragma unroll
    for (int i = 0; i < 8; i++) {
        int r = rb + 8 * i;
        *(float4*)(KV + r * HD + c4)      = vr[i][0];
        *(float4*)(KV + r * HD + c4 + 32) = vr[i][1];
    }
    __syncthreads();

    // ---- GEMM2: O = P @ V
    u64 oa[8][4];
    #pragma unroll
    for (int j = 0; j < 8; j++) { oa[j][0]=oa[j][1]=oa[j][2]=oa[j][3]=0ull; }
    #pragma unroll 4
    for (int m = 0; m < WSZ; m++) {
        float4 v0 = *(const float4*)(KV + m * HD + c0);
        float4 v1 = *(const float4*)(KV + m * HD + c0 + 32);
        ulonglong2 pA = *(const ulonglong2*)(Qt + SW(m, r0));
        ulonglong2 pB = *(const ulonglong2*)(Qt + SW(m, r0 + 4));
        u64 pp[4] = {pA.x, pA.y, pB.x, pB.y};
        u64 vd[8] = {pk2(v0.x,v0.x), pk2(v0.y,v0.y), pk2(v0.z,v0.z), pk2(v0.w,v0.w),
                     pk2(v1.x,v1.x), pk2(v1.y,v1.y), pk2(v1.z,v1.z), pk2(v1.w,v1.w)};
        #pragma unroll
        for (int j = 0; j < 8; j++)
            #pragma unroll
            for (int p = 0; p < 4; p++) ffma2(oa[j][p], pp[p], vd[j]);
    }

    // ---- output store (roll folded back in)
    #pragma unroll
    for (int p = 0; p < 4; p++) {
        float o[2][8];
        #pragma unroll
        for (int j = 0; j < 8; j++) upk2(oa[j][p], o[0][j], o[1][j]);
        #pragma unroll
        for (int s = 0; s < 2; s++) {
            int g = (wstart + r0 + 2*p + s + SHIFT) & (WTOT - 1);
            *(float4*)(xout + base + (size_t)g*HD + c0)      = make_float4(o[s][0],o[s][1],o[s][2],o[s][3]);
            *(float4*)(xout + base + (size_t)g*HD + c0 + 32) = make_float4(o[s][4],o[s][5],o[s][6],o[s][7]);
        }
    }
}

extern "C" void kernel_launch(void* const* d_in, const int* in_sizes, int n_in,
                              void* d_out, int out_size) {
    const float* q   = (const float*)d_in[0];
    const float* k   = (const float*)d_in[1];
    const float* v   = (const float*)d_in[2];
    const float* rel = (const float*)d_in[3];
    const int B = in_sizes[0] / (WTOT * HD);
    float* xout = (float*)d_out;
    float* aout = xout + (size_t)B * WTOT * HD;

    // 32KB smem/CTA -> 7 CTAs/SM needs 224KB shared carveout.
    cudaFuncSetAttribute(swin_attn8,
                         cudaFuncAttributePreferredSharedMemoryCarveout, 100);

    swin_attn8<<<B * NWIN, 64>>>(q, k, v, rel, xout, aout);
}

// round 17
// speedup vs baseline: 1.4227x; 1.3098x over previous
#include <cuda_runtime.h>
#include <cstdint>

#define WSZ 64
#define HD 64
#define SHIFT 32
#define WTOT 8192
#define NWIN 128

// dynamic smem layout (floats): Qs[64*64] | Ks[64*64] | Vs[64*72]
#define QS_OFF 0
#define KS_OFF 4096
#define VS_OFF 8192
#define VSTRIDE 72
#define SMEM_FLOATS (4096 + 4096 + 64 * VSTRIDE)
#define SMEM_BYTES (SMEM_FLOATS * 4)

// XOR-swizzled index into [64][64] row-major tiles (float4-granular swizzle)
__device__ __forceinline__ int SWI(int r, int f) {
    return (r << 6) + (f ^ ((r & 7) << 2));
}
__device__ __forceinline__ uint32_t f2tf(float x) {
    uint32_t r; asm("cvt.rna.tf32.f32 %0, %1;" : "=r"(r) : "f"(x)); return r;
}
// d += A(16x8) * B(8x8), tf32 inputs, f32 accum
__device__ __forceinline__ void mma8(float* d, const uint32_t* a, const uint32_t* b) {
    asm("mma.sync.aligned.m16n8k8.row.col.f32.tf32.tf32.f32 "
        "{%0,%1,%2,%3},{%4,%5,%6,%7},{%8,%9},{%0,%1,%2,%3};"
        : "+f"(d[0]), "+f"(d[1]), "+f"(d[2]), "+f"(d[3])
        : "r"(a[0]), "r"(a[1]), "r"(a[2]), "r"(a[3]), "r"(b[0]), "r"(b[1]));
}
// load fp32, split into (big, small) tf32 pair: x ~= big + small to ~2^-21
__device__ __forceinline__ void split(float x, uint32_t& b, uint32_t& s) {
    b = f2tf(x);
    s = f2tf(x - __uint_as_float(b));
}

__global__ __launch_bounds__(128, 4)
void swin_mma(const float* __restrict__ q, const float* __restrict__ k,
              const float* __restrict__ v, const float* __restrict__ rel,
              float* __restrict__ xout, float* __restrict__ aout)
{
    extern __shared__ float sm[];
    float* Qs = sm + QS_OFF;   // [m][k] swizzled; later P[m][k]
    float* Ks = sm + KS_OFF;   // [n][k] swizzled
    float* Vs = sm + VS_OFF;   // [k][n] stride-72 padded

    const int t = threadIdx.x, blk = blockIdx.x;
    const int w = blk & (NWIN - 1);
    const size_t base = (size_t)(blk >> 7) * (size_t)(WTOT * HD);
    const int wstart = w * WSZ;

    // ---- loaders: fully-coalesced float4, roll folded into row index ----
    #pragma unroll
    for (int i = 0; i < 8; i++) {
        int idx = t + 128 * i;           // 0..1023 float4 slots
        int r = idx >> 4;                // 0..63
        int c4 = (idx & 15) << 2;        // 0..60
        int g = (wstart + r + SHIFT) & (WTOT - 1);
        size_t off = base + (size_t)g * HD + c4;
        float4 qv = *(const float4*)(q + off);
        float4 kv = *(const float4*)(k + off);
        float4 vv = *(const float4*)(v + off);
        int sA = SWI(r, c4);
        // swizzle preserves 16B granularity -> float4 store OK; phase conflict-free
        *(float4*)(Qs + sA) = make_float4(qv.x * 0.125f, qv.y * 0.125f,
                                          qv.z * 0.125f, qv.w * 0.125f);
        *(float4*)(Ks + sA) = kv;
        *(float4*)(Vs + r * VSTRIDE + c4) = vv;
    }
    __syncthreads();

    const int wid = t >> 5, lane = t & 31;
    const int g8 = lane >> 2, tau = lane & 3;    // groupID, threadID_in_group
    const int M0 = wid << 4;
    const int rA = M0 + g8, rB = rA + 8;

    // ---- GEMM1: S = (Q*scale) @ K^T via 3xTF32 mma ----
    float dS[8][4];
    #pragma unroll
    for (int n = 0; n < 8; n++) { dS[n][0]=dS[n][1]=dS[n][2]=dS[n][3]=0.f; }

    #pragma unroll
    for (int kt = 0; kt < 8; kt++) {
        int k0 = kt * 8;
        uint32_t ab[4], as_[4];
        split(Qs[SWI(rA, k0 + tau)],     ab[0], as_[0]);
        split(Qs[SWI(rB, k0 + tau)],     ab[1], as_[1]);
        split(Qs[SWI(rA, k0 + tau + 4)], ab[2], as_[2]);
        split(Qs[SWI(rB, k0 + tau + 4)], ab[3], as_[3]);
        #pragma unroll
        for (int nt = 0; nt < 8; nt++) {
            uint32_t bb[2], bs[2];
            split(Ks[SWI(nt * 8 + g8, k0 + tau)],     bb[0], bs[0]);
            split(Ks[SWI(nt * 8 + g8, k0 + tau + 4)], bb[1], bs[1]);
            mma8(dS[nt], ab, bb);
            mma8(dS[nt], as_, bb);
            mma8(dS[nt], ab, bs);
        }
    }

    // ---- bias + shift mask ----
    const bool lastw = (w == NWIN - 1);
    const bool rAhi = (rA >= SHIFT), rBhi = (rB >= SHIFT);
    #pragma unroll
    for (int nt = 0; nt < 8; nt++) {
        int cA = nt * 8 + 2 * tau;
        int bidx = rA - cA + 63;
        dS[nt][0] += __ldg(rel + bidx);
        dS[nt][1] += __ldg(rel + bidx - 1);
        dS[nt][2] += __ldg(rel + bidx + 8);
        dS[nt][3] += __ldg(rel + bidx + 7);
        if (lastw) {
            bool chi = (nt >= 4);                 // cols 8nt..8nt+7 one side
            if (rAhi != chi) { dS[nt][0] -= 100.f; dS[nt][1] -= 100.f; }
            if (rBhi != chi) { dS[nt][2] -= 100.f; dS[nt][3] -= 100.f; }
        }
    }

    // ---- softmax: row rA over regs {0,1}, row rB over {2,3}; quad shuffles ----
    float mA = -1e30f, mB = -1e30f;
    #pragma unroll
    for (int nt = 0; nt < 8; nt++) {
        mA = fmaxf(mA, fmaxf(dS[nt][0], dS[nt][1]));
        mB = fmaxf(mB, fmaxf(dS[nt][2], dS[nt][3]));
    }
    mA = fmaxf(mA, __shfl_xor_sync(~0u, mA, 1));
    mA = fmaxf(mA, __shfl_xor_sync(~0u, mA, 2));
    mB = fmaxf(mB, __shfl_xor_sync(~0u, mB, 1));
    mB = fmaxf(mB, __shfl_xor_sync(~0u, mB, 2));
    float sA = 0.f, sB = 0.f;
    #pragma unroll
    for (int nt = 0; nt < 8; nt++) {
        dS[nt][0] = __expf(dS[nt][0] - mA); sA += dS[nt][0];
        dS[nt][1] = __expf(dS[nt][1] - mA); sA += dS[nt][1];
        dS[nt][2] = __expf(dS[nt][2] - mB); sB += dS[nt][2];
        dS[nt][3] = __expf(dS[nt][3] - mB); sB += dS[nt][3];
    }
    sA += __shfl_xor_sync(~0u, sA, 1); sA += __shfl_xor_sync(~0u, sA, 2);
    sB += __shfl_xor_sync(~0u, sB, 1); sB += __shfl_xor_sync(~0u, sB, 2);
    float iA = __fdividef(1.f, sA), iB = __fdividef(1.f, sB);

    // ---- normalize, store attn (global) and P (smem, reuse Qs rows M0..M0+15) ----
    const size_t aoff = (size_t)blk * (WSZ * WSZ);
    #pragma unroll
    for (int nt = 0; nt < 8; nt++) {
        dS[nt][0] *= iA; dS[nt][1] *= iA; dS[nt][2] *= iB; dS[nt][3] *= iB;
        int cA = nt * 8 + 2 * tau;
        *(float2*)(aout + aoff + (size_t)rA * WSZ + cA) = make_float2(dS[nt][0], dS[nt][1]);
        *(float2*)(aout + aoff + (size_t)rB * WSZ + cA) = make_float2(dS[nt][2], dS[nt][3]);
        // P into Qs: each warp touches only its own 16 rows -> no CTA barrier
        *(float2*)(Qs + SWI(rA, cA)) = make_float2(dS[nt][0], dS[nt][1]);
        *(float2*)(Qs + SWI(rB, cA)) = make_float2(dS[nt][2], dS[nt][3]);
    }
    __syncwarp();

    // ---- GEMM2: O = P @ V via 3xTF32 mma ----
    float dO[8][4];
    #pragma unroll
    for (int n = 0; n < 8; n++) { dO[n][0]=dO[n][1]=dO[n][2]=dO[n][3]=0.f; }

    #pragma unroll
    for (int kt = 0; kt < 8; kt++) {
        int k0 = kt * 8;
        uint32_t ab[4], as_[4];
        split(Qs[SWI(rA, k0 + tau)],     ab[0], as_[0]);
        split(Qs[SWI(rB, k0 + tau)],     ab[1], as_[1]);
        split(Qs[SWI(rA, k0 + tau + 4)], ab[2], as_[2]);
        split(Qs[SWI(rB, k0 + tau + 4)], ab[3], as_[3]);
        #pragma unroll
        for (int nt = 0; nt < 8; nt++) {
            uint32_t bb[2], bs[2];
            split(Vs[(k0 + tau) * VSTRIDE + nt * 8 + g8],     bb[0], bs[0]);
            split(Vs[(k0 + tau + 4) * VSTRIDE + nt * 8 + g8], bb[1], bs[1]);
            mma8(dO[nt], ab, bb);
            mma8(dO[nt], as_, bb);
            mma8(dO[nt], ab, bs);
        }
    }

    // ---- output store (roll folded back in) ----
    const int gA = (wstart + rA + SHIFT) & (WTOT - 1);
    const int gB = (wstart + rB + SHIFT) & (WTOT - 1);
    #pragma unroll
    for (int nt = 0; nt < 8; nt++) {
        int cA = nt * 8 + 2 * tau;
        *(float2*)(xout + base + (size_t)gA * HD + cA) = make_float2(dO[nt][0], dO[nt][1]);
        *(float2*)(xout + base + (size_t)gB * HD + cA) = make_float2(dO[nt][2], dO[nt][3]);
    }
}

extern "C" void kernel_launch(void* const* d_in, const int* in_sizes, int n_in,
                              void* d_out, int out_size) {
    const float* q   = (const float*)d_in[0];
    const float* k   = (const float*)d_in[1];
    const float* v   = (const float*)d_in[2];
    const float* rel = (const float*)d_in[3];
    const int B = in_sizes[0] / (WTOT * HD);
    float* xout = (float*)d_out;
    float* aout = xout + (size_t)B * WTOT * HD;

    cudaFuncSetAttribute(swin_mma,
                         cudaFuncAttributeMaxDynamicSharedMemorySize, SMEM_BYTES);
    cudaFuncSetAttribute(swin_mma,
                         cudaFuncAttributePreferredSharedMemoryCarveout, 100);

    swin_mma<<<B * NWIN, 128, SMEM_BYTES>>>(q, k, v, rel, xout, aout);
}